// round 10
// baseline (speedup 1.0000x reference)
#include <cuda_runtime.h>
#include <cuda_bf16.h>
#include <math.h>
#include <stdint.h>

// ---------------------------------------------------------------------------
// Problem constants
// ---------------------------------------------------------------------------
constexpr int B_  = 4;
constexpr int T_  = 2048;
constexpr int D_  = 1024;
constexpr int M1  = B_ * T_;        // 8192
constexpr int N1  = 4 * D_;         // 4096
constexpr int K1  = D_;             // 1024
constexpr int K2  = 2 * D_;         // 2048
constexpr int N2  = D_;             // 1024
constexpr int NCHUNK = 32;
constexpr int LCH = T_ / NCHUNK;    // 64

// ---------------------------------------------------------------------------
// Scratch (static device globals — no allocation allowed)
// ---------------------------------------------------------------------------
__device__ float g_u[(size_t)M1 * N1];
__device__ float g_y[(size_t)M1 * K2];
__device__ float g_cBr[B_ * NCHUNK * D_];
__device__ float g_cBi[B_ * NCHUNK * D_];
__device__ float g_carR[B_ * NCHUNK * D_];
__device__ float g_carI[B_ * NCHUNK * D_];

__device__ __nv_bfloat16 g_xh[(size_t)M1 * K1];
__device__ __nv_bfloat16 g_xl[(size_t)M1 * K1];
__device__ __nv_bfloat16 g_w1h[(size_t)N1 * K1];   // W_in^T  [4096,1024]
__device__ __nv_bfloat16 g_w1l[(size_t)N1 * K1];
__device__ __nv_bfloat16 g_yh[(size_t)M1 * K2];
__device__ __nv_bfloat16 g_yl[(size_t)M1 * K2];
__device__ __nv_bfloat16 g_w2h[(size_t)N2 * K2];   // W_out^T [1024,2048]
__device__ __nv_bfloat16 g_w2l[(size_t)N2 * K2];

// ---------------------------------------------------------------------------
// PTX helpers
// ---------------------------------------------------------------------------
__device__ __forceinline__ uint32_t smem_u32(const void* p) {
    uint32_t a;
    asm("{ .reg .u64 t; cvta.to.shared.u64 t, %1; cvt.u32.u64 %0, t; }"
        : "=r"(a) : "l"(p));
    return a;
}

__device__ __forceinline__ void cp16(uint32_t dst, const void* src) {
    asm volatile("cp.async.cg.shared.global [%0], [%1], 16;\n" :: "r"(dst), "l"(src) : "memory");
}
#define CP_COMMIT() asm volatile("cp.async.commit_group;" ::: "memory")

__device__ __forceinline__ void ldm_x4(uint32_t* r, uint32_t addr) {
    asm volatile("ldmatrix.sync.aligned.m8n8.x4.shared.b16 {%0,%1,%2,%3}, [%4];"
                 : "=r"(r[0]), "=r"(r[1]), "=r"(r[2]), "=r"(r[3]) : "r"(addr));
}

__device__ __forceinline__ void mma_bf16(float* d, const uint32_t* a, uint32_t b0, uint32_t b1) {
    asm volatile(
        "mma.sync.aligned.m16n8k16.row.col.f32.bf16.bf16.f32 "
        "{%0,%1,%2,%3}, {%4,%5,%6,%7}, {%8,%9}, {%0,%1,%2,%3};"
        : "+f"(d[0]), "+f"(d[1]), "+f"(d[2]), "+f"(d[3])
        : "r"(a[0]), "r"(a[1]), "r"(a[2]), "r"(a[3]), "r"(b0), "r"(b1));
}

// ---------------------------------------------------------------------------
// bf16-split MMA GEMM: C[M,N] = A[M,K] @ Bt[N,K]^T + bias
// 256x128 block tile, BK=32, 8 warps as 4m x 2n (warp tile 64x64).
// 3-stage cp.async ring, ONE __syncthreads per stage, grid swizzled.
// SMEM slot (48KB): Ah@0(16K) Al@16K Bh@32K(8K) Bl@40K ; rows 64B, XOR swizzle.
// ---------------------------------------------------------------------------
constexpr int NSTAGE    = 3;
constexpr int SLOT      = 49152;
constexpr int GEMM_SMEM = NSTAGE * SLOT;   // 144 KB -> 1 CTA/SM

__device__ __forceinline__ uint32_t sw_off(int row, int kch) {
    return (uint32_t)(row * 64 + ((kch ^ ((row >> 1) & 3)) << 4));
}

__global__ __launch_bounds__(256, 1)
void mma_gemm(int M, int N, int K,
              const __nv_bfloat16* __restrict__ Ah, const __nv_bfloat16* __restrict__ Al,
              const __nv_bfloat16* __restrict__ Bh, const __nv_bfloat16* __restrict__ Bl,
              const float* __restrict__ bias, float* __restrict__ C)
{
    extern __shared__ char smem[];
    const uint32_t sb = smem_u32(smem);
    const int tid  = threadIdx.x;
    const int lane = tid & 31;
    const int wid  = tid >> 5;
    const int wm   = wid & 3;        // 4 warps along M (64 rows each)
    const int wn   = wid >> 2;       // 2 warps along N (64 cols each)

    // grid swizzle: 8-row bands of M-tiles, column-minor inside band
    const int nbx  = N >> 7;
    const int lin  = blockIdx.x;
    const int band = lin / (8 * nbx);
    const int rem  = lin % (8 * nbx);
    const int by   = band * 8 + (rem & 7);
    const int bx   = rem >> 3;

    const size_t arow0 = (size_t)by * 256;
    const size_t brow0 = (size_t)bx * 128;
    const int S = K / 32;

    float acc[4][8][4];
    #pragma unroll
    for (int i = 0; i < 4; i++)
        #pragma unroll
        for (int j = 0; j < 8; j++)
            #pragma unroll
            for (int k = 0; k < 4; k++) acc[i][j][k] = 0.f;

    auto load_stage = [&](int s, int slot) {
        const uint32_t st = sb + (uint32_t)slot * (uint32_t)SLOT;
        const int k0 = s * 32;
        // A hi/lo: 256 rows x 4 chunks = 1024 chunks each
        #pragma unroll
        for (int j = 0; j < 4; j++) {
            const int idx = tid + j * 256;
            const int r = idx >> 2, c = idx & 3;
            cp16(st +          sw_off(r, c), Ah + (arow0 + r) * (size_t)K + k0 + c * 8);
            cp16(st + 16384u + sw_off(r, c), Al + (arow0 + r) * (size_t)K + k0 + c * 8);
        }
        // B hi/lo: 128 rows x 4 chunks = 512 chunks each
        #pragma unroll
        for (int j = 0; j < 2; j++) {
            const int idx = tid + j * 256;
            const int r = idx >> 2, c = idx & 3;
            cp16(st + 32768u + sw_off(r, c), Bh + (brow0 + r) * (size_t)K + k0 + c * 8);
            cp16(st + 40960u + sw_off(r, c), Bl + (brow0 + r) * (size_t)K + k0 + c * 8);
        }
    };

    const int sub = lane >> 3;
    const int r8  = lane & 7;

    load_stage(0, 0); CP_COMMIT();
    load_stage(1, 1); CP_COMMIT();

    int slot_c = 0;   // compute slot
    int slot_l = 2;   // next load slot
    for (int s = 0; s < S; s++) {
        // one group committed per iteration -> wait 1 == stage s resident
        asm volatile("cp.async.wait_group 1;" ::: "memory");
        __syncthreads();

        if (s + 2 < S) load_stage(s + 2, slot_l);
        CP_COMMIT();

        const uint32_t st = sb + (uint32_t)slot_c * (uint32_t)SLOT;
        #pragma unroll
        for (int ks = 0; ks < 2; ks++) {
            uint32_t aH[4][4], aL[4][4];
            #pragma unroll
            for (int mi = 0; mi < 4; mi++) {
                const int mrow = wm * 64 + mi * 16 + (sub & 1) * 8 + r8;
                const int kch  = ks * 2 + (sub >> 1);
                ldm_x4(aH[mi], st +          sw_off(mrow, kch));
                ldm_x4(aL[mi], st + 16384u + sw_off(mrow, kch));
            }
            #pragma unroll
            for (int np = 0; np < 4; np++) {
                uint32_t bH[4], bL[4];
                const int nrow = wn * 64 + np * 16 + (sub >> 1) * 8 + r8;
                const int kch  = ks * 2 + (sub & 1);
                ldm_x4(bH, st + 32768u + sw_off(nrow, kch));
                ldm_x4(bL, st + 40960u + sw_off(nrow, kch));
                #pragma unroll
                for (int mi = 0; mi < 4; mi++) {
                    #pragma unroll
                    for (int hh = 0; hh < 2; hh++) {
                        float* d = acc[mi][np * 2 + hh];
                        mma_bf16(d, aH[mi], bH[hh * 2], bH[hh * 2 + 1]);
                        mma_bf16(d, aH[mi], bL[hh * 2], bL[hh * 2 + 1]);
                        mma_bf16(d, aL[mi], bH[hh * 2], bH[hh * 2 + 1]);
                    }
                }
            }
        }
        slot_c = (slot_c == 2) ? 0 : slot_c + 1;
        slot_l = (slot_l == 2) ? 0 : slot_l + 1;
    }

    // Epilogue
    #pragma unroll
    for (int mi = 0; mi < 4; mi++) {
        const size_t r0 = arow0 + wm * 64 + mi * 16 + (lane >> 2);
        #pragma unroll
        for (int ni = 0; ni < 8; ni++) {
            const int c = bx * 128 + wn * 64 + ni * 8 + (lane & 3) * 2;
            const float b0 = bias[c], b1 = bias[c + 1];
            float2 v0 = make_float2(acc[mi][ni][0] + b0, acc[mi][ni][1] + b1);
            float2 v1 = make_float2(acc[mi][ni][2] + b0, acc[mi][ni][3] + b1);
            *reinterpret_cast<float2*>(C + r0 * (size_t)N + c)       = v0;
            *reinterpret_cast<float2*>(C + (r0 + 8) * (size_t)N + c) = v1;
        }
    }
}

// ---------------------------------------------------------------------------
// fp32 -> bf16 hi/lo split
// ---------------------------------------------------------------------------
__global__ void split_rows(const float* __restrict__ X,
                           __nv_bfloat16* __restrict__ Xh,
                           __nv_bfloat16* __restrict__ Xl, size_t n)
{
    size_t i = ((size_t)blockIdx.x * blockDim.x + threadIdx.x) * 4;
    if (i >= n) return;
    float4 v = *reinterpret_cast<const float4*>(X + i);
    __nv_bfloat16 h0 = __float2bfloat16_rn(v.x);
    __nv_bfloat16 h1 = __float2bfloat16_rn(v.y);
    __nv_bfloat16 h2 = __float2bfloat16_rn(v.z);
    __nv_bfloat16 h3 = __float2bfloat16_rn(v.w);
    __nv_bfloat162 hA = __nv_bfloat162(h0, h1), hB = __nv_bfloat162(h2, h3);
    __nv_bfloat162 lA = __nv_bfloat162(__float2bfloat16_rn(v.x - __bfloat162float(h0)),
                                       __float2bfloat16_rn(v.y - __bfloat162float(h1)));
    __nv_bfloat162 lB = __nv_bfloat162(__float2bfloat16_rn(v.z - __bfloat162float(h2)),
                                       __float2bfloat16_rn(v.w - __bfloat162float(h3)));
    *reinterpret_cast<__nv_bfloat162*>(Xh + i)     = hA;
    *reinterpret_cast<__nv_bfloat162*>(Xh + i + 2) = hB;
    *reinterpret_cast<__nv_bfloat162*>(Xl + i)     = lA;
    *reinterpret_cast<__nv_bfloat162*>(Xl + i + 2) = lB;
}

// ---------------------------------------------------------------------------
// W[K,N] -> T[N,K] transpose + bf16 hi/lo split
// ---------------------------------------------------------------------------
__global__ void transpose_split(const float* __restrict__ W, int K, int N,
                                __nv_bfloat16* __restrict__ Th,
                                __nv_bfloat16* __restrict__ Tl)
{
    __shared__ float tile[32][33];
    int n0 = blockIdx.x * 32, k0 = blockIdx.y * 32;
    int tx = threadIdx.x, ty = threadIdx.y;
    #pragma unroll
    for (int i = 0; i < 32; i += 8)
        tile[ty + i][tx] = W[(size_t)(k0 + ty + i) * N + n0 + tx];
    __syncthreads();
    #pragma unroll
    for (int i = 0; i < 32; i += 8) {
        int nn = ty + i, kk = tx;
        float v = tile[kk][nn];
        __nv_bfloat16 h = __float2bfloat16_rn(v);
        Th[(size_t)(n0 + nn) * K + k0 + kk] = h;
        Tl[(size_t)(n0 + nn) * K + k0 + kk] = __float2bfloat16_rn(v - __bfloat162float(h));
    }
}

// ---------------------------------------------------------------------------
// LRU scan (3-phase chunked, 32 chunks x 64 steps)
// ---------------------------------------------------------------------------
__device__ __forceinline__ void chan_params(const float* __restrict__ nu_log,
                                            const float* __restrict__ theta_log,
                                            const float* __restrict__ gamma_log,
                                            int d, float& fr, float& fi, float& ga)
{
    float nu = expf(-expf(nu_log[d]));
    float th = expf(theta_log[d]);
    fr = nu * cosf(th);
    fi = nu * sinf(th);
    ga = expf(gamma_log[d]);
}

__global__ void scan_phase1(const float* __restrict__ nu_log,
                            const float* __restrict__ theta_log,
                            const float* __restrict__ gamma_log)
{
    int idx = blockIdx.x * blockDim.x + threadIdx.x;
    int d = idx % D_;
    int c = (idx / D_) % NCHUNK;
    int b = idx / (D_ * NCHUNK);

    float fr, fi, ga;
    chan_params(nu_log, theta_log, gamma_log, d, fr, fi, ga);

    const float* up = g_u + (size_t)(b * T_ + c * LCH) * N1;
    float hr = 0.f, hi = 0.f;
    #pragma unroll 4
    for (int t = 0; t < LCH; t++) {
        float vr = ga * up[(size_t)t * N1 + d];
        float vi = ga * up[(size_t)t * N1 + D_ + d];
        float nr = fr * hr - fi * hi + vr;
        float ni = fr * hi + fi * hr + vi;
        hr = nr; hi = ni;
    }
    g_cBr[idx] = hr;
    g_cBi[idx] = hi;
}

__global__ void scan_phase2(const float* __restrict__ nu_log,
                            const float* __restrict__ theta_log)
{
    int idx = blockIdx.x * blockDim.x + threadIdx.x;
    int d = idx % D_;
    int b = idx / D_;

    float nu = expf(-expf(nu_log[d]));
    float th = expf(theta_log[d]);
    float ar = nu * cosf(th);
    float ai = nu * sinf(th);
    // f^64 via 6 complex squarings
    #pragma unroll
    for (int s = 0; s < 6; s++) {
        float nr = ar * ar - ai * ai;
        float ni = 2.f * ar * ai;
        ar = nr; ai = ni;
    }

    float cr = 0.f, ci = 0.f;
    for (int c = 0; c < NCHUNK; c++) {
        int o = (b * NCHUNK + c) * D_ + d;
        g_carR[o] = cr;
        g_carI[o] = ci;
        float br = g_cBr[o], bi = g_cBi[o];
        float nr = ar * cr - ai * ci + br;
        float ni = ar * ci + ai * cr + bi;
        cr = nr; ci = ni;
    }
}

__global__ void scan_phase3(const float* __restrict__ nu_log,
                            const float* __restrict__ theta_log,
                            const float* __restrict__ gamma_log)
{
    int idx = blockIdx.x * blockDim.x + threadIdx.x;
    int d = idx % D_;
    int c = (idx / D_) % NCHUNK;
    int b = idx / (D_ * NCHUNK);

    float fr, fi, ga;
    chan_params(nu_log, theta_log, gamma_log, d, fr, fi, ga);

    int o = (b * NCHUNK + c) * D_ + d;
    float hr = g_carR[o], hi = g_carI[o];

    const float* up = g_u + (size_t)(b * T_ + c * LCH) * N1;
    float*       yp = g_y + (size_t)(b * T_ + c * LCH) * K2;

    #pragma unroll 4
    for (int t = 0; t < LCH; t++) {
        float vr = ga * up[(size_t)t * N1 + d];
        float vi = ga * up[(size_t)t * N1 + D_ + d];
        float o1 = up[(size_t)t * N1 + 2 * D_ + d];
        float o2 = up[(size_t)t * N1 + 3 * D_ + d];
        float nr = fr * hr - fi * hi + vr;
        float ni = fr * hi + fi * hr + vi;
        hr = nr; hi = ni;
        float s1 = o1 / (1.f + expf(-o1));
        float s2 = o2 / (1.f + expf(-o2));
        yp[(size_t)t * K2 + d]       = hr * s1;
        yp[(size_t)t * K2 + D_ + d]  = hi * s2;
    }
}

// ---------------------------------------------------------------------------
// LayerNorm(2048) fused with bf16 hi/lo split: g_y -> g_yh/g_yl
// ---------------------------------------------------------------------------
__global__ void ln_split_kernel(const float* __restrict__ ln_w,
                                const float* __restrict__ ln_b)
{
    const int row = blockIdx.x;
    const float* yp = g_y + (size_t)row * K2;
    __nv_bfloat16* yh = g_yh + (size_t)row * K2;
    __nv_bfloat16* yl = g_yl + (size_t)row * K2;

    float lsum = 0.f, lsq = 0.f;
    for (int i = threadIdx.x; i < K2; i += blockDim.x) {
        float v = yp[i];
        lsum += v;
        lsq  += v * v;
    }
    #pragma unroll
    for (int off = 16; off > 0; off >>= 1) {
        lsum += __shfl_xor_sync(0xFFFFFFFF, lsum, off);
        lsq  += __shfl_xor_sync(0xFFFFFFFF, lsq,  off);
    }
    __shared__ float s1[8], s2[8];
    int wid = threadIdx.x >> 5, lane = threadIdx.x & 31;
    if (lane == 0) { s1[wid] = lsum; s2[wid] = lsq; }
    __syncthreads();
    if (wid == 0) {
        float a = (lane < 8) ? s1[lane] : 0.f;
        float b = (lane < 8) ? s2[lane] : 0.f;
        #pragma unroll
        for (int off = 4; off > 0; off >>= 1) {
            a += __shfl_xor_sync(0xFFFFFFFF, a, off);
            b += __shfl_xor_sync(0xFFFFFFFF, b, off);
        }
        if (lane == 0) { s1[0] = a; s2[0] = b; }
    }
    __syncthreads();
    float mean = s1[0] / K2;
    float var  = s2[0] / K2 - mean * mean;
    float inv  = rsqrtf(var + 1e-5f);

    for (int i = threadIdx.x; i < K2; i += blockDim.x) {
        float v = (yp[i] - mean) * inv * ln_w[i] + ln_b[i];
        __nv_bfloat16 h = __float2bfloat16_rn(v);
        yh[i] = h;
        yl[i] = __float2bfloat16_rn(v - __bfloat162float(h));
    }
}

// ---------------------------------------------------------------------------
// Launch
// ---------------------------------------------------------------------------
extern "C" void kernel_launch(void* const* d_in, const int* in_sizes, int n_in,
                              void* d_out, int out_size)
{
    const float* x         = (const float*)d_in[0];
    const float* W_in      = (const float*)d_in[1];
    const float* b_in      = (const float*)d_in[2];
    const float* nu_log    = (const float*)d_in[3];
    const float* theta_log = (const float*)d_in[4];
    const float* gamma_log = (const float*)d_in[5];
    const float* ln_w      = (const float*)d_in[6];
    const float* ln_b      = (const float*)d_in[7];
    const float* W_out     = (const float*)d_in[8];
    const float* b_out     = (const float*)d_in[9];
    float* out = (float*)d_out;

    float *u_ptr;
    cudaGetSymbolAddress((void**)&u_ptr, g_u);
    __nv_bfloat16 *xh, *xl, *w1h, *w1l, *yh, *yl, *w2h, *w2l;
    cudaGetSymbolAddress((void**)&xh,  g_xh);
    cudaGetSymbolAddress((void**)&xl,  g_xl);
    cudaGetSymbolAddress((void**)&w1h, g_w1h);
    cudaGetSymbolAddress((void**)&w1l, g_w1l);
    cudaGetSymbolAddress((void**)&yh,  g_yh);
    cudaGetSymbolAddress((void**)&yl,  g_yl);
    cudaGetSymbolAddress((void**)&w2h, g_w2h);
    cudaGetSymbolAddress((void**)&w2l, g_w2l);

    cudaFuncSetAttribute(mma_gemm, cudaFuncAttributeMaxDynamicSharedMemorySize, GEMM_SMEM);

    // operand prep for GEMM1
    {
        size_t n = (size_t)M1 * K1;
        split_rows<<<(unsigned)((n / 4 + 255) / 256), 256>>>(x, xh, xl, n);
        dim3 g(N1 / 32, K1 / 32);
        transpose_split<<<g, dim3(32, 8)>>>(W_in, K1, N1, w1h, w1l);
    }
    // GEMM1: u = x @ W_in + b_in
    {
        int grid = (M1 / 256) * (N1 / 128);
        mma_gemm<<<grid, 256, GEMM_SMEM>>>(M1, N1, K1, xh, xl, w1h, w1l, b_in, u_ptr);
    }
    // Scan (3-phase)
    {
        int total = B_ * NCHUNK * D_;
        scan_phase1<<<total / 256, 256>>>(nu_log, theta_log, gamma_log);
        scan_phase2<<<(B_ * D_) / 256, 256>>>(nu_log, theta_log);
        scan_phase3<<<total / 256, 256>>>(nu_log, theta_log, gamma_log);
    }
    // LayerNorm + bf16 split fused
    ln_split_kernel<<<M1, 256>>>(ln_w, ln_b);

    // operand prep for GEMM2 (weights only; y already split)
    {
        dim3 g(N2 / 32, K2 / 32);
        transpose_split<<<g, dim3(32, 8)>>>(W_out, K2, N2, w2h, w2l);
    }
    // GEMM2: out = y @ W_out + b_out
    {
        int grid = (M1 / 256) * (N2 / 128);
        mma_gemm<<<grid, 256, GEMM_SMEM>>>(M1, N2, K2, yh, yl, w2h, w2l, b_out, out);
    }
}

// round 13
// speedup vs baseline: 1.1396x; 1.1396x over previous
#include <cuda_runtime.h>
#include <cuda_bf16.h>
#include <math.h>
#include <stdint.h>

// ---------------------------------------------------------------------------
// Problem constants
// ---------------------------------------------------------------------------
constexpr int B_  = 4;
constexpr int T_  = 2048;
constexpr int D_  = 1024;
constexpr int M1  = B_ * T_;        // 8192
constexpr int N1  = 4 * D_;         // 4096
constexpr int K1  = D_;             // 1024
constexpr int K2  = 2 * D_;         // 2048
constexpr int N2  = D_;             // 1024
constexpr int NCHUNK = 32;
constexpr int LCH = T_ / NCHUNK;    // 64

// ---------------------------------------------------------------------------
// Scratch (static device globals — no allocation allowed)
// ---------------------------------------------------------------------------
__device__ float g_u[(size_t)M1 * N1];
__device__ float g_y[(size_t)M1 * K2];
__device__ float g_cBr[B_ * NCHUNK * D_];
__device__ float g_cBi[B_ * NCHUNK * D_];
__device__ float g_carR[B_ * NCHUNK * D_];
__device__ float g_carI[B_ * NCHUNK * D_];

__device__ __nv_bfloat16 g_xh[(size_t)M1 * K1];
__device__ __nv_bfloat16 g_xl[(size_t)M1 * K1];
__device__ __nv_bfloat16 g_w1h[(size_t)N1 * K1];   // W_in^T  [4096,1024]
__device__ __nv_bfloat16 g_w1l[(size_t)N1 * K1];
__device__ __nv_bfloat16 g_yh[(size_t)M1 * K2];
__device__ __nv_bfloat16 g_yl[(size_t)M1 * K2];
__device__ __nv_bfloat16 g_w2h[(size_t)N2 * K2];   // W_out^T [1024,2048]
__device__ __nv_bfloat16 g_w2l[(size_t)N2 * K2];

// ---------------------------------------------------------------------------
// PTX helpers
// ---------------------------------------------------------------------------
__device__ __forceinline__ uint32_t smem_u32(const void* p) {
    uint32_t a;
    asm("{ .reg .u64 t; cvta.to.shared.u64 t, %1; cvt.u32.u64 %0, t; }"
        : "=r"(a) : "l"(p));
    return a;
}

__device__ __forceinline__ void cp16(uint32_t dst, const void* src) {
    asm volatile("cp.async.cg.shared.global [%0], [%1], 16;\n" :: "r"(dst), "l"(src) : "memory");
}
#define CP_COMMIT() asm volatile("cp.async.commit_group;" ::: "memory")

__device__ __forceinline__ void ldm_x4(uint32_t* r, uint32_t addr) {
    asm volatile("ldmatrix.sync.aligned.m8n8.x4.shared.b16 {%0,%1,%2,%3}, [%4];"
                 : "=r"(r[0]), "=r"(r[1]), "=r"(r[2]), "=r"(r[3]) : "r"(addr));
}

__device__ __forceinline__ void mma_bf16(float* d, const uint32_t* a, uint32_t b0, uint32_t b1) {
    asm volatile(
        "mma.sync.aligned.m16n8k16.row.col.f32.bf16.bf16.f32 "
        "{%0,%1,%2,%3}, {%4,%5,%6,%7}, {%8,%9}, {%0,%1,%2,%3};"
        : "+f"(d[0]), "+f"(d[1]), "+f"(d[2]), "+f"(d[3])
        : "r"(a[0]), "r"(a[1]), "r"(a[2]), "r"(a[3]), "r"(b0), "r"(b1));
}

// ---------------------------------------------------------------------------
// bf16-split MMA GEMM: C[M,N] = A[M,K] @ Bt[N,K]^T + bias
// 128x128 block tile, BK=32, 4 warps as 2m x 2n (warp tile 64x64).
// 3-stage cp.async ring, 2 CTAs/SM, ONE __syncthreads per stage, grid swizzled.
// SMEM slot (32KB): Ah@0 Al@8K Bh@16K Bl@24K (each 128 rows x 64B, XOR swizzle)
// ---------------------------------------------------------------------------
constexpr int NSTAGE    = 3;
constexpr int SLOT      = 32768;
constexpr int GEMM_SMEM = NSTAGE * SLOT;   // 96 KB -> 2 CTAs/SM

__device__ __forceinline__ uint32_t sw_off(int row, int kch) {
    return (uint32_t)(row * 64 + ((kch ^ ((row >> 1) & 3)) << 4));
}

__global__ __launch_bounds__(128, 2)
void mma_gemm(int M, int N, int K,
              const __nv_bfloat16* __restrict__ Ah, const __nv_bfloat16* __restrict__ Al,
              const __nv_bfloat16* __restrict__ Bh, const __nv_bfloat16* __restrict__ Bl,
              const float* __restrict__ bias, float* __restrict__ C)
{
    extern __shared__ char smem[];
    const uint32_t sb = smem_u32(smem);
    const int tid  = threadIdx.x;
    const int lane = tid & 31;
    const int wid  = tid >> 5;
    const int wm   = wid & 1;        // 2 warps along M (64 rows each)
    const int wn   = wid >> 1;       // 2 warps along N (64 cols each)

    // grid swizzle: 8-row bands, column-minor inside band
    const int nbx  = N >> 7;
    const int lin  = blockIdx.x;
    const int band = lin / (8 * nbx);
    const int rem  = lin % (8 * nbx);
    const int by   = band * 8 + (rem & 7);
    const int bx   = rem >> 3;

    const size_t arow0 = (size_t)by * 128;
    const size_t brow0 = (size_t)bx * 128;
    const int S = K / 32;

    float acc[4][8][4];
    #pragma unroll
    for (int i = 0; i < 4; i++)
        #pragma unroll
        for (int j = 0; j < 8; j++)
            #pragma unroll
            for (int k = 0; k < 4; k++) acc[i][j][k] = 0.f;

    auto load_stage = [&](int s, int slot) {
        const uint32_t st = sb + (uint32_t)slot * (uint32_t)SLOT;
        const int k0 = s * 32;
        // each tile: 128 rows x 4 chunks = 512 chunks; 128 threads -> 4 each
        #pragma unroll
        for (int j = 0; j < 4; j++) {
            const int idx = tid + j * 128;
            const int r = idx >> 2, c = idx & 3;
            cp16(st +          sw_off(r, c), Ah + (arow0 + r) * (size_t)K + k0 + c * 8);
            cp16(st + 8192u  + sw_off(r, c), Al + (arow0 + r) * (size_t)K + k0 + c * 8);
            cp16(st + 16384u + sw_off(r, c), Bh + (brow0 + r) * (size_t)K + k0 + c * 8);
            cp16(st + 24576u + sw_off(r, c), Bl + (brow0 + r) * (size_t)K + k0 + c * 8);
        }
    };

    const int sub = lane >> 3;
    const int r8  = lane & 7;

    load_stage(0, 0); CP_COMMIT();
    load_stage(1, 1); CP_COMMIT();

    int slot_c = 0;   // compute slot
    int slot_l = 2;   // next load slot
    for (int s = 0; s < S; s++) {
        // one group committed per iteration -> wait 1 == stage s resident;
        // barrier also protects slot_l reuse (computed at iter s-1)
        asm volatile("cp.async.wait_group 1;" ::: "memory");
        __syncthreads();

        if (s + 2 < S) load_stage(s + 2, slot_l);
        CP_COMMIT();

        const uint32_t st = sb + (uint32_t)slot_c * (uint32_t)SLOT;
        #pragma unroll
        for (int ks = 0; ks < 2; ks++) {
            uint32_t aH[4][4], aL[4][4];
            #pragma unroll
            for (int mi = 0; mi < 4; mi++) {
                const int mrow = wm * 64 + mi * 16 + (sub & 1) * 8 + r8;
                const int kch  = ks * 2 + (sub >> 1);
                ldm_x4(aH[mi], st +         sw_off(mrow, kch));
                ldm_x4(aL[mi], st + 8192u + sw_off(mrow, kch));
            }
            #pragma unroll
            for (int np = 0; np < 4; np++) {
                uint32_t bH[4], bL[4];
                const int nrow = wn * 64 + np * 16 + (sub >> 1) * 8 + r8;
                const int kch  = ks * 2 + (sub & 1);
                ldm_x4(bH, st + 16384u + sw_off(nrow, kch));
                ldm_x4(bL, st + 24576u + sw_off(nrow, kch));
                #pragma unroll
                for (int mi = 0; mi < 4; mi++) {
                    #pragma unroll
                    for (int hh = 0; hh < 2; hh++) {
                        float* d = acc[mi][np * 2 + hh];
                        mma_bf16(d, aH[mi], bH[hh * 2], bH[hh * 2 + 1]);
                        mma_bf16(d, aH[mi], bL[hh * 2], bL[hh * 2 + 1]);
                        mma_bf16(d, aL[mi], bH[hh * 2], bH[hh * 2 + 1]);
                    }
                }
            }
        }
        slot_c = (slot_c == 2) ? 0 : slot_c + 1;
        slot_l = (slot_l == 2) ? 0 : slot_l + 1;
    }

    // Epilogue
    #pragma unroll
    for (int mi = 0; mi < 4; mi++) {
        const size_t r0 = arow0 + wm * 64 + mi * 16 + (lane >> 2);
        #pragma unroll
        for (int ni = 0; ni < 8; ni++) {
            const int c = bx * 128 + wn * 64 + ni * 8 + (lane & 3) * 2;
            const float b0 = bias[c], b1 = bias[c + 1];
            float2 v0 = make_float2(acc[mi][ni][0] + b0, acc[mi][ni][1] + b1);
            float2 v1 = make_float2(acc[mi][ni][2] + b0, acc[mi][ni][3] + b1);
            *reinterpret_cast<float2*>(C + r0 * (size_t)N + c)       = v0;
            *reinterpret_cast<float2*>(C + (r0 + 8) * (size_t)N + c) = v1;
        }
    }
}

// ---------------------------------------------------------------------------
// fp32 -> bf16 hi/lo split
// ---------------------------------------------------------------------------
__global__ void split_rows(const float* __restrict__ X,
                           __nv_bfloat16* __restrict__ Xh,
                           __nv_bfloat16* __restrict__ Xl, size_t n)
{
    size_t i = ((size_t)blockIdx.x * blockDim.x + threadIdx.x) * 4;
    if (i >= n) return;
    float4 v = *reinterpret_cast<const float4*>(X + i);
    __nv_bfloat16 h0 = __float2bfloat16_rn(v.x);
    __nv_bfloat16 h1 = __float2bfloat16_rn(v.y);
    __nv_bfloat16 h2 = __float2bfloat16_rn(v.z);
    __nv_bfloat16 h3 = __float2bfloat16_rn(v.w);
    __nv_bfloat162 hA = __nv_bfloat162(h0, h1), hB = __nv_bfloat162(h2, h3);
    __nv_bfloat162 lA = __nv_bfloat162(__float2bfloat16_rn(v.x - __bfloat162float(h0)),
                                       __float2bfloat16_rn(v.y - __bfloat162float(h1)));
    __nv_bfloat162 lB = __nv_bfloat162(__float2bfloat16_rn(v.z - __bfloat162float(h2)),
                                       __float2bfloat16_rn(v.w - __bfloat162float(h3)));
    *reinterpret_cast<__nv_bfloat162*>(Xh + i)     = hA;
    *reinterpret_cast<__nv_bfloat162*>(Xh + i + 2) = hB;
    *reinterpret_cast<__nv_bfloat162*>(Xl + i)     = lA;
    *reinterpret_cast<__nv_bfloat162*>(Xl + i + 2) = lB;
}

// ---------------------------------------------------------------------------
// W[K,N] -> T[N,K] transpose + bf16 hi/lo split
// ---------------------------------------------------------------------------
__global__ void transpose_split(const float* __restrict__ W, int K, int N,
                                __nv_bfloat16* __restrict__ Th,
                                __nv_bfloat16* __restrict__ Tl)
{
    __shared__ float tile[32][33];
    int n0 = blockIdx.x * 32, k0 = blockIdx.y * 32;
    int tx = threadIdx.x, ty = threadIdx.y;
    #pragma unroll
    for (int i = 0; i < 32; i += 8)
        tile[ty + i][tx] = W[(size_t)(k0 + ty + i) * N + n0 + tx];
    __syncthreads();
    #pragma unroll
    for (int i = 0; i < 32; i += 8) {
        int nn = ty + i, kk = tx;
        float v = tile[kk][nn];
        __nv_bfloat16 h = __float2bfloat16_rn(v);
        Th[(size_t)(n0 + nn) * K + k0 + kk] = h;
        Tl[(size_t)(n0 + nn) * K + k0 + kk] = __float2bfloat16_rn(v - __bfloat162float(h));
    }
}

// ---------------------------------------------------------------------------
// LRU scan (3-phase chunked, 32 chunks x 64 steps)
// ---------------------------------------------------------------------------
__device__ __forceinline__ void chan_params(const float* __restrict__ nu_log,
                                            const float* __restrict__ theta_log,
                                            const float* __restrict__ gamma_log,
                                            int d, float& fr, float& fi, float& ga)
{
    float nu = expf(-expf(nu_log[d]));
    float th = expf(theta_log[d]);
    fr = nu * cosf(th);
    fi = nu * sinf(th);
    ga = expf(gamma_log[d]);
}

__global__ void scan_phase1(const float* __restrict__ nu_log,
                            const float* __restrict__ theta_log,
                            const float* __restrict__ gamma_log)
{
    int idx = blockIdx.x * blockDim.x + threadIdx.x;
    int d = idx % D_;
    int c = (idx / D_) % NCHUNK;
    int b = idx / (D_ * NCHUNK);

    float fr, fi, ga;
    chan_params(nu_log, theta_log, gamma_log, d, fr, fi, ga);

    const float* up = g_u + (size_t)(b * T_ + c * LCH) * N1;
    float hr = 0.f, hi = 0.f;
    #pragma unroll 4
    for (int t = 0; t < LCH; t++) {
        float vr = ga * up[(size_t)t * N1 + d];
        float vi = ga * up[(size_t)t * N1 + D_ + d];
        float nr = fr * hr - fi * hi + vr;
        float ni = fr * hi + fi * hr + vi;
        hr = nr; hi = ni;
    }
    g_cBr[idx] = hr;
    g_cBi[idx] = hi;
}

__global__ void scan_phase2(const float* __restrict__ nu_log,
                            const float* __restrict__ theta_log)
{
    int idx = blockIdx.x * blockDim.x + threadIdx.x;
    int d = idx % D_;
    int b = idx / D_;

    float nu = expf(-expf(nu_log[d]));
    float th = expf(theta_log[d]);
    float ar = nu * cosf(th);
    float ai = nu * sinf(th);
    // f^64 via 6 complex squarings
    #pragma unroll
    for (int s = 0; s < 6; s++) {
        float nr = ar * ar - ai * ai;
        float ni = 2.f * ar * ai;
        ar = nr; ai = ni;
    }

    float cr = 0.f, ci = 0.f;
    for (int c = 0; c < NCHUNK; c++) {
        int o = (b * NCHUNK + c) * D_ + d;
        g_carR[o] = cr;
        g_carI[o] = ci;
        float br = g_cBr[o], bi = g_cBi[o];
        float nr = ar * cr - ai * ci + br;
        float ni = ar * ci + ai * cr + bi;
        cr = nr; ci = ni;
    }
}

__global__ void scan_phase3(const float* __restrict__ nu_log,
                            const float* __restrict__ theta_log,
                            const float* __restrict__ gamma_log)
{
    int idx = blockIdx.x * blockDim.x + threadIdx.x;
    int d = idx % D_;
    int c = (idx / D_) % NCHUNK;
    int b = idx / (D_ * NCHUNK);

    float fr, fi, ga;
    chan_params(nu_log, theta_log, gamma_log, d, fr, fi, ga);

    int o = (b * NCHUNK + c) * D_ + d;
    float hr = g_carR[o], hi = g_carI[o];

    const float* up = g_u + (size_t)(b * T_ + c * LCH) * N1;
    float*       yp = g_y + (size_t)(b * T_ + c * LCH) * K2;

    #pragma unroll 4
    for (int t = 0; t < LCH; t++) {
        float vr = ga * up[(size_t)t * N1 + d];
        float vi = ga * up[(size_t)t * N1 + D_ + d];
        float o1 = up[(size_t)t * N1 + 2 * D_ + d];
        float o2 = up[(size_t)t * N1 + 3 * D_ + d];
        float nr = fr * hr - fi * hi + vr;
        float ni = fr * hi + fi * hr + vi;
        hr = nr; hi = ni;
        float s1 = o1 / (1.f + expf(-o1));
        float s2 = o2 / (1.f + expf(-o2));
        yp[(size_t)t * K2 + d]       = hr * s1;
        yp[(size_t)t * K2 + D_ + d]  = hi * s2;
    }
}

// ---------------------------------------------------------------------------
// LayerNorm(2048) fused with bf16 hi/lo split: g_y -> g_yh/g_yl
// ---------------------------------------------------------------------------
__global__ void ln_split_kernel(const float* __restrict__ ln_w,
                                const float* __restrict__ ln_b)
{
    const int row = blockIdx.x;
    const float* yp = g_y + (size_t)row * K2;
    __nv_bfloat16* yh = g_yh + (size_t)row * K2;
    __nv_bfloat16* yl = g_yl + (size_t)row * K2;

    float lsum = 0.f, lsq = 0.f;
    for (int i = threadIdx.x; i < K2; i += blockDim.x) {
        float v = yp[i];
        lsum += v;
        lsq  += v * v;
    }
    #pragma unroll
    for (int off = 16; off > 0; off >>= 1) {
        lsum += __shfl_xor_sync(0xFFFFFFFF, lsum, off);
        lsq  += __shfl_xor_sync(0xFFFFFFFF, lsq,  off);
    }
    __shared__ float s1[8], s2[8];
    int wid = threadIdx.x >> 5, lane = threadIdx.x & 31;
    if (lane == 0) { s1[wid] = lsum; s2[wid] = lsq; }
    __syncthreads();
    if (wid == 0) {
        float a = (lane < 8) ? s1[lane] : 0.f;
        float b = (lane < 8) ? s2[lane] : 0.f;
        #pragma unroll
        for (int off = 4; off > 0; off >>= 1) {
            a += __shfl_xor_sync(0xFFFFFFFF, a, off);
            b += __shfl_xor_sync(0xFFFFFFFF, b, off);
        }
        if (lane == 0) { s1[0] = a; s2[0] = b; }
    }
    __syncthreads();
    float mean = s1[0] / K2;
    float var  = s2[0] / K2 - mean * mean;
    float inv  = rsqrtf(var + 1e-5f);

    for (int i = threadIdx.x; i < K2; i += blockDim.x) {
        float v = (yp[i] - mean) * inv * ln_w[i] + ln_b[i];
        __nv_bfloat16 h = __float2bfloat16_rn(v);
        yh[i] = h;
        yl[i] = __float2bfloat16_rn(v - __bfloat162float(h));
    }
}

// ---------------------------------------------------------------------------
// Launch
// ---------------------------------------------------------------------------
extern "C" void kernel_launch(void* const* d_in, const int* in_sizes, int n_in,
                              void* d_out, int out_size)
{
    const float* x         = (const float*)d_in[0];
    const float* W_in      = (const float*)d_in[1];
    const float* b_in      = (const float*)d_in[2];
    const float* nu_log    = (const float*)d_in[3];
    const float* theta_log = (const float*)d_in[4];
    const float* gamma_log = (const float*)d_in[5];
    const float* ln_w      = (const float*)d_in[6];
    const float* ln_b      = (const float*)d_in[7];
    const float* W_out     = (const float*)d_in[8];
    const float* b_out     = (const float*)d_in[9];
    float* out = (float*)d_out;

    float *u_ptr;
    cudaGetSymbolAddress((void**)&u_ptr, g_u);
    __nv_bfloat16 *xh, *xl, *w1h, *w1l, *yh, *yl, *w2h, *w2l;
    cudaGetSymbolAddress((void**)&xh,  g_xh);
    cudaGetSymbolAddress((void**)&xl,  g_xl);
    cudaGetSymbolAddress((void**)&w1h, g_w1h);
    cudaGetSymbolAddress((void**)&w1l, g_w1l);
    cudaGetSymbolAddress((void**)&yh,  g_yh);
    cudaGetSymbolAddress((void**)&yl,  g_yl);
    cudaGetSymbolAddress((void**)&w2h, g_w2h);
    cudaGetSymbolAddress((void**)&w2l, g_w2l);

    cudaFuncSetAttribute(mma_gemm, cudaFuncAttributeMaxDynamicSharedMemorySize, GEMM_SMEM);

    // operand prep for GEMM1
    {
        size_t n = (size_t)M1 * K1;
        split_rows<<<(unsigned)((n / 4 + 255) / 256), 256>>>(x, xh, xl, n);
        dim3 g(N1 / 32, K1 / 32);
        transpose_split<<<g, dim3(32, 8)>>>(W_in, K1, N1, w1h, w1l);
    }
    // GEMM1: u = x @ W_in + b_in
    {
        int grid = (M1 / 128) * (N1 / 128);
        mma_gemm<<<grid, 128, GEMM_SMEM>>>(M1, N1, K1, xh, xl, w1h, w1l, b_in, u_ptr);
    }
    // Scan (3-phase)
    {
        int total = B_ * NCHUNK * D_;
        scan_phase1<<<total / 256, 256>>>(nu_log, theta_log, gamma_log);
        scan_phase2<<<(B_ * D_) / 256, 256>>>(nu_log, theta_log);
        scan_phase3<<<total / 256, 256>>>(nu_log, theta_log, gamma_log);
    }
    // LayerNorm + bf16 split fused
    ln_split_kernel<<<M1, 256>>>(ln_w, ln_b);

    // operand prep for GEMM2 (weights only; y already split)
    {
        dim3 g(N2 / 32, K2 / 32);
        transpose_split<<<g, dim3(32, 8)>>>(W_out, K2, N2, w2h, w2l);
    }
    // GEMM2: out = y @ W_out + b_out
    {
        int grid = (M1 / 128) * (N2 / 128);
        mma_gemm<<<grid, 128, GEMM_SMEM>>>(M1, N2, K2, yh, yl, w2h, w2l, b_out, out);
    }
}

// round 16
// speedup vs baseline: 1.3600x; 1.1934x over previous
#include <cuda_runtime.h>
#include <cuda_bf16.h>
#include <math.h>
#include <stdint.h>

// ---------------------------------------------------------------------------
// Problem constants
// ---------------------------------------------------------------------------
constexpr int B_  = 4;
constexpr int T_  = 2048;
constexpr int D_  = 1024;
constexpr int M1  = B_ * T_;        // 8192
constexpr int N1  = 4 * D_;         // 4096
constexpr int K1  = D_;             // 1024
constexpr int K2  = 2 * D_;         // 2048
constexpr int N2  = D_;             // 1024
constexpr int NCHUNK = 32;
constexpr int LCH = T_ / NCHUNK;    // 64

// ---------------------------------------------------------------------------
// Scratch (static device globals — no allocation allowed)
// ---------------------------------------------------------------------------
__device__ float g_u[(size_t)M1 * N1];      // u = x@W_in + b_in
__device__ float g_y[(size_t)M1 * K2];      // gated scan output (pre-LN)
__device__ float g_cBr[B_ * NCHUNK * D_];
__device__ float g_cBi[B_ * NCHUNK * D_];
__device__ float g_carR[B_ * NCHUNK * D_];
__device__ float g_carI[B_ * NCHUNK * D_];

// tf32-rounded operands (stored as fp32 with low mantissa zeroed)
__device__ float g_xt [(size_t)M1 * K1];
__device__ float g_w1t[(size_t)N1 * K1];    // W_in^T  [4096,1024]
__device__ float g_yt [(size_t)M1 * K2];    // LN output, tf32-rounded
__device__ float g_w2t[(size_t)N2 * K2];    // W_out^T [1024,2048]

// ---------------------------------------------------------------------------
// PTX helpers
// ---------------------------------------------------------------------------
__device__ __forceinline__ uint32_t smem_u32(const void* p) {
    uint32_t a;
    asm("{ .reg .u64 t; cvta.to.shared.u64 t, %1; cvt.u32.u64 %0, t; }"
        : "=r"(a) : "l"(p));
    return a;
}

__device__ __forceinline__ void cp16(uint32_t dst, const void* src) {
    asm volatile("cp.async.cg.shared.global [%0], [%1], 16;\n" :: "r"(dst), "l"(src) : "memory");
}
#define CP_COMMIT() asm volatile("cp.async.commit_group;" ::: "memory")

__device__ __forceinline__ float to_tf32(float x) {
    uint32_t u;
    asm("cvt.rna.tf32.f32 %0, %1;" : "=r"(u) : "f"(x));
    return __uint_as_float(u);
}

__device__ __forceinline__ void mma_tf32(float* d, const uint32_t* a, uint32_t b0, uint32_t b1) {
    asm volatile(
        "mma.sync.aligned.m16n8k8.row.col.f32.tf32.tf32.f32 "
        "{%0,%1,%2,%3}, {%4,%5,%6,%7}, {%8,%9}, {%0,%1,%2,%3};"
        : "+f"(d[0]), "+f"(d[1]), "+f"(d[2]), "+f"(d[3])
        : "r"(a[0]), "r"(a[1]), "r"(a[2]), "r"(a[3]), "r"(b0), "r"(b1));
}

// ---------------------------------------------------------------------------
// tf32 MMA GEMM: C[M,N] = A[M,K] @ Bt[N,K]^T + bias   (A, Bt tf32-pre-rounded)
// 128x128 block tile, BK=32, 4 warps as 2m x 2n (warp tile 64x64).
// 3-stage cp.async ring, 2 CTAs/SM, ONE __syncthreads per stage, grid swizzled.
// SMEM slot (32KB): A@0 (128 rows x 128B), B@16K (128 rows x 128B), XOR swizzle
// on 16B chunks: ch ^= row & 7.
// ---------------------------------------------------------------------------
constexpr int NSTAGE    = 3;
constexpr int SLOT      = 32768;
constexpr int GEMM_SMEM = NSTAGE * SLOT;   // 96 KB -> 2 CTAs/SM

__device__ __forceinline__ uint32_t sw32(int row, int ch) {
    return (uint32_t)(row * 128 + (((ch) ^ (row & 7)) << 4));
}

__global__ __launch_bounds__(128, 2)
void tf32_gemm(int M, int N, int K,
               const float* __restrict__ A, const float* __restrict__ Bt,
               const float* __restrict__ bias, float* __restrict__ C)
{
    extern __shared__ char smem[];
    const uint32_t sb = smem_u32(smem);
    const int tid  = threadIdx.x;
    const int lane = tid & 31;
    const int wid  = tid >> 5;
    const int wm   = wid & 1;        // 2 warps along M (64 rows each)
    const int wn   = wid >> 1;       // 2 warps along N (64 cols each)

    // grid swizzle: 8-row bands, column-minor inside band
    const int nbx  = N >> 7;
    const int lin  = blockIdx.x;
    const int band = lin / (8 * nbx);
    const int rem  = lin % (8 * nbx);
    const int by   = band * 8 + (rem & 7);
    const int bx   = rem >> 3;

    const size_t arow0 = (size_t)by * 128;
    const size_t brow0 = (size_t)bx * 128;
    const int S = K / 32;

    float acc[4][8][4];
    #pragma unroll
    for (int i = 0; i < 4; i++)
        #pragma unroll
        for (int j = 0; j < 8; j++)
            #pragma unroll
            for (int k = 0; k < 4; k++) acc[i][j][k] = 0.f;

    auto load_stage = [&](int s, int slot) {
        const uint32_t st = sb + (uint32_t)slot * (uint32_t)SLOT;
        const int k0 = s * 32;
        // A,B tiles: 128 rows x 8 chunks(16B) = 1024 chunks each; 128 thr -> 8 each
        #pragma unroll
        for (int j = 0; j < 8; j++) {
            const int idx = tid + j * 128;
            const int r = idx >> 3, ch = idx & 7;
            cp16(st +          sw32(r, ch), A  + (arow0 + r) * (size_t)K + k0 + ch * 4);
            cp16(st + 16384u + sw32(r, ch), Bt + (brow0 + r) * (size_t)K + k0 + ch * 4);
        }
    };

    const int rA = lane >> 2;        // 0..7
    const int cb = (lane & 3) * 4;   // byte offset within 16B chunk

    load_stage(0, 0); CP_COMMIT();
    load_stage(1, 1); CP_COMMIT();

    int slot_c = 0;
    int slot_l = 2;
    for (int s = 0; s < S; s++) {
        // one group committed per iteration -> wait 1 == stage s resident;
        // barrier also protects slot_l reuse
        asm volatile("cp.async.wait_group 1;" ::: "memory");
        __syncthreads();

        if (s + 2 < S) load_stage(s + 2, slot_l);
        CP_COMMIT();

        const char* baseA = smem + slot_c * SLOT;
        const char* baseB = baseA + 16384;
        #pragma unroll
        for (int ks8 = 0; ks8 < 4; ks8++) {
            const int ch0 = ks8 * 2, ch1 = ch0 + 1;
            const uint32_t x0 = (uint32_t)(((ch0 ^ rA) << 4) + cb);
            const uint32_t x1 = (uint32_t)(((ch1 ^ rA) << 4) + cb);

            uint32_t aF[4][4];
            #pragma unroll
            for (int mi = 0; mi < 4; mi++) {
                const int r0 = wm * 64 + mi * 16 + rA;
                aF[mi][0] = *(const uint32_t*)(baseA + r0 * 128 + x0);
                aF[mi][1] = *(const uint32_t*)(baseA + (r0 + 8) * 128 + x0);
                aF[mi][2] = *(const uint32_t*)(baseA + r0 * 128 + x1);
                aF[mi][3] = *(const uint32_t*)(baseA + (r0 + 8) * 128 + x1);
            }
            #pragma unroll
            for (int np = 0; np < 8; np++) {
                const int rn = wn * 64 + np * 8 + rA;
                const uint32_t b0 = *(const uint32_t*)(baseB + rn * 128 + x0);
                const uint32_t b1 = *(const uint32_t*)(baseB + rn * 128 + x1);
                #pragma unroll
                for (int mi = 0; mi < 4; mi++)
                    mma_tf32(acc[mi][np], aF[mi], b0, b1);
            }
        }
        slot_c = (slot_c == 2) ? 0 : slot_c + 1;
        slot_l = (slot_l == 2) ? 0 : slot_l + 1;
    }

    // Epilogue
    #pragma unroll
    for (int mi = 0; mi < 4; mi++) {
        const size_t r0 = arow0 + wm * 64 + mi * 16 + (lane >> 2);
        #pragma unroll
        for (int ni = 0; ni < 8; ni++) {
            const int c = bx * 128 + wn * 64 + ni * 8 + (lane & 3) * 2;
            const float b0 = bias[c], b1 = bias[c + 1];
            float2 v0 = make_float2(acc[mi][ni][0] + b0, acc[mi][ni][1] + b1);
            float2 v1 = make_float2(acc[mi][ni][2] + b0, acc[mi][ni][3] + b1);
            *reinterpret_cast<float2*>(C + r0 * (size_t)N + c)       = v0;
            *reinterpret_cast<float2*>(C + (r0 + 8) * (size_t)N + c) = v1;
        }
    }
}

// ---------------------------------------------------------------------------
// fp32 -> tf32 round (elementwise)
// ---------------------------------------------------------------------------
__global__ void round_rows(const float* __restrict__ X, float* __restrict__ Xt, size_t n)
{
    size_t i = ((size_t)blockIdx.x * blockDim.x + threadIdx.x) * 4;
    if (i >= n) return;
    float4 v = *reinterpret_cast<const float4*>(X + i);
    v.x = to_tf32(v.x); v.y = to_tf32(v.y);
    v.z = to_tf32(v.z); v.w = to_tf32(v.w);
    *reinterpret_cast<float4*>(Xt + i) = v;
}

// ---------------------------------------------------------------------------
// W[K,N] -> T[N,K] transpose + tf32 round
// ---------------------------------------------------------------------------
__global__ void transpose_round(const float* __restrict__ W, int K, int N,
                                float* __restrict__ Tt)
{
    __shared__ float tile[32][33];
    int n0 = blockIdx.x * 32, k0 = blockIdx.y * 32;
    int tx = threadIdx.x, ty = threadIdx.y;
    #pragma unroll
    for (int i = 0; i < 32; i += 8)
        tile[ty + i][tx] = W[(size_t)(k0 + ty + i) * N + n0 + tx];
    __syncthreads();
    #pragma unroll
    for (int i = 0; i < 32; i += 8) {
        int nn = ty + i, kk = tx;
        Tt[(size_t)(n0 + nn) * K + k0 + kk] = to_tf32(tile[kk][nn]);
    }
}

// ---------------------------------------------------------------------------
// LRU scan (3-phase chunked, 32 chunks x 64 steps)
// ---------------------------------------------------------------------------
__device__ __forceinline__ void chan_params(const float* __restrict__ nu_log,
                                            const float* __restrict__ theta_log,
                                            const float* __restrict__ gamma_log,
                                            int d, float& fr, float& fi, float& ga)
{
    float nu = expf(-expf(nu_log[d]));
    float th = expf(theta_log[d]);
    fr = nu * cosf(th);
    fi = nu * sinf(th);
    ga = expf(gamma_log[d]);
}

__global__ void scan_phase1(const float* __restrict__ nu_log,
                            const float* __restrict__ theta_log,
                            const float* __restrict__ gamma_log)
{
    int idx = blockIdx.x * blockDim.x + threadIdx.x;
    int d = idx % D_;
    int c = (idx / D_) % NCHUNK;
    int b = idx / (D_ * NCHUNK);

    float fr, fi, ga;
    chan_params(nu_log, theta_log, gamma_log, d, fr, fi, ga);

    const float* up = g_u + (size_t)(b * T_ + c * LCH) * N1;
    float hr = 0.f, hi = 0.f;
    #pragma unroll 4
    for (int t = 0; t < LCH; t++) {
        float vr = ga * up[(size_t)t * N1 + d];
        float vi = ga * up[(size_t)t * N1 + D_ + d];
        float nr = fr * hr - fi * hi + vr;
        float ni = fr * hi + fi * hr + vi;
        hr = nr; hi = ni;
    }
    g_cBr[idx] = hr;
    g_cBi[idx] = hi;
}

__global__ void scan_phase2(const float* __restrict__ nu_log,
                            const float* __restrict__ theta_log)
{
    int idx = blockIdx.x * blockDim.x + threadIdx.x;
    int d = idx % D_;
    int b = idx / D_;

    float nu = expf(-expf(nu_log[d]));
    float th = expf(theta_log[d]);
    float ar = nu * cosf(th);
    float ai = nu * sinf(th);
    // f^64 via 6 complex squarings
    #pragma unroll
    for (int s = 0; s < 6; s++) {
        float nr = ar * ar - ai * ai;
        float ni = 2.f * ar * ai;
        ar = nr; ai = ni;
    }

    float cr = 0.f, ci = 0.f;
    for (int c = 0; c < NCHUNK; c++) {
        int o = (b * NCHUNK + c) * D_ + d;
        g_carR[o] = cr;
        g_carI[o] = ci;
        float br = g_cBr[o], bi = g_cBi[o];
        float nr = ar * cr - ai * ci + br;
        float ni = ar * ci + ai * cr + bi;
        cr = nr; ci = ni;
    }
}

__global__ void scan_phase3(const float* __restrict__ nu_log,
                            const float* __restrict__ theta_log,
                            const float* __restrict__ gamma_log)
{
    int idx = blockIdx.x * blockDim.x + threadIdx.x;
    int d = idx % D_;
    int c = (idx / D_) % NCHUNK;
    int b = idx / (D_ * NCHUNK);

    float fr, fi, ga;
    chan_params(nu_log, theta_log, gamma_log, d, fr, fi, ga);

    int o = (b * NCHUNK + c) * D_ + d;
    float hr = g_carR[o], hi = g_carI[o];

    const float* up = g_u + (size_t)(b * T_ + c * LCH) * N1;
    float*       yp = g_y + (size_t)(b * T_ + c * LCH) * K2;

    #pragma unroll 4
    for (int t = 0; t < LCH; t++) {
        float vr = ga * up[(size_t)t * N1 + d];
        float vi = ga * up[(size_t)t * N1 + D_ + d];
        float o1 = up[(size_t)t * N1 + 2 * D_ + d];
        float o2 = up[(size_t)t * N1 + 3 * D_ + d];
        float nr = fr * hr - fi * hi + vr;
        float ni = fr * hi + fi * hr + vi;
        hr = nr; hi = ni;
        float s1 = o1 / (1.f + expf(-o1));
        float s2 = o2 / (1.f + expf(-o2));
        yp[(size_t)t * K2 + d]       = hr * s1;
        yp[(size_t)t * K2 + D_ + d]  = hi * s2;
    }
}

// ---------------------------------------------------------------------------
// LayerNorm(2048) fused with tf32 round: g_y -> g_yt
// ---------------------------------------------------------------------------
__global__ void ln_round_kernel(const float* __restrict__ ln_w,
                                const float* __restrict__ ln_b)
{
    const int row = blockIdx.x;
    const float* yp = g_y  + (size_t)row * K2;
    float*       yt = g_yt + (size_t)row * K2;

    float lsum = 0.f, lsq = 0.f;
    for (int i = threadIdx.x; i < K2; i += blockDim.x) {
        float v = yp[i];
        lsum += v;
        lsq  += v * v;
    }
    #pragma unroll
    for (int off = 16; off > 0; off >>= 1) {
        lsum += __shfl_xor_sync(0xFFFFFFFF, lsum, off);
        lsq  += __shfl_xor_sync(0xFFFFFFFF, lsq,  off);
    }
    __shared__ float s1[8], s2[8];
    int wid = threadIdx.x >> 5, lane = threadIdx.x & 31;
    if (lane == 0) { s1[wid] = lsum; s2[wid] = lsq; }
    __syncthreads();
    if (wid == 0) {
        float a = (lane < 8) ? s1[lane] : 0.f;
        float b = (lane < 8) ? s2[lane] : 0.f;
        #pragma unroll
        for (int off = 4; off > 0; off >>= 1) {
            a += __shfl_xor_sync(0xFFFFFFFF, a, off);
            b += __shfl_xor_sync(0xFFFFFFFF, b, off);
        }
        if (lane == 0) { s1[0] = a; s2[0] = b; }
    }
    __syncthreads();
    float mean = s1[0] / K2;
    float var  = s2[0] / K2 - mean * mean;
    float inv  = rsqrtf(var + 1e-5f);

    for (int i = threadIdx.x; i < K2; i += blockDim.x) {
        float v = (yp[i] - mean) * inv * ln_w[i] + ln_b[i];
        yt[i] = to_tf32(v);
    }
}

// ---------------------------------------------------------------------------
// Launch
// ---------------------------------------------------------------------------
extern "C" void kernel_launch(void* const* d_in, const int* in_sizes, int n_in,
                              void* d_out, int out_size)
{
    const float* x         = (const float*)d_in[0];
    const float* W_in      = (const float*)d_in[1];
    const float* b_in      = (const float*)d_in[2];
    const float* nu_log    = (const float*)d_in[3];
    const float* theta_log = (const float*)d_in[4];
    const float* gamma_log = (const float*)d_in[5];
    const float* ln_w      = (const float*)d_in[6];
    const float* ln_b      = (const float*)d_in[7];
    const float* W_out     = (const float*)d_in[8];
    const float* b_out     = (const float*)d_in[9];
    float* out = (float*)d_out;

    float *u_ptr, *xt, *w1t, *yt, *w2t;
    cudaGetSymbolAddress((void**)&u_ptr, g_u);
    cudaGetSymbolAddress((void**)&xt,  g_xt);
    cudaGetSymbolAddress((void**)&w1t, g_w1t);
    cudaGetSymbolAddress((void**)&yt,  g_yt);
    cudaGetSymbolAddress((void**)&w2t, g_w2t);

    cudaFuncSetAttribute(tf32_gemm, cudaFuncAttributeMaxDynamicSharedMemorySize, GEMM_SMEM);

    // operand prep for GEMM1
    {
        size_t n = (size_t)M1 * K1;
        round_rows<<<(unsigned)((n / 4 + 255) / 256), 256>>>(x, xt, n);
        dim3 g(N1 / 32, K1 / 32);
        transpose_round<<<g, dim3(32, 8)>>>(W_in, K1, N1, w1t);
    }
    // GEMM1: u = x @ W_in + b_in
    {
        int grid = (M1 / 128) * (N1 / 128);
        tf32_gemm<<<grid, 128, GEMM_SMEM>>>(M1, N1, K1, xt, w1t, b_in, u_ptr);
    }
    // Scan (3-phase)
    {
        int total = B_ * NCHUNK * D_;
        scan_phase1<<<total / 256, 256>>>(nu_log, theta_log, gamma_log);
        scan_phase2<<<(B_ * D_) / 256, 256>>>(nu_log, theta_log);
        scan_phase3<<<total / 256, 256>>>(nu_log, theta_log, gamma_log);
    }
    // LayerNorm + tf32 round fused
    ln_round_kernel<<<M1, 256>>>(ln_w, ln_b);

    // operand prep for GEMM2 (weights only; y already rounded)
    {
        dim3 g(N2 / 32, K2 / 32);
        transpose_round<<<g, dim3(32, 8)>>>(W_out, K2, N2, w2t);
    }
    // GEMM2: out = y @ W_out + b_out
    {
        int grid = (M1 / 128) * (N2 / 128);
        tf32_gemm<<<grid, 128, GEMM_SMEM>>>(M1, N2, K2, yt, w2t, b_out, out);
    }
}

// round 17
// speedup vs baseline: 1.4288x; 1.0506x over previous
#include <cuda_runtime.h>
#include <cuda_bf16.h>
#include <math.h>
#include <stdint.h>

// ---------------------------------------------------------------------------
// Problem constants
// ---------------------------------------------------------------------------
constexpr int B_  = 4;
constexpr int T_  = 2048;
constexpr int D_  = 1024;
constexpr int M1  = B_ * T_;        // 8192
constexpr int N1  = 4 * D_;         // 4096
constexpr int K1  = D_;             // 1024
constexpr int K2  = 2 * D_;         // 2048
constexpr int N2  = D_;             // 1024
constexpr int NCHUNK = 64;
constexpr int LCH = T_ / NCHUNK;    // 32

// ---------------------------------------------------------------------------
// Scratch (static device globals — no allocation allowed)
// ---------------------------------------------------------------------------
__device__ float g_u[(size_t)M1 * N1];      // u = x@W_in + b_in
__device__ float g_cBr[B_ * NCHUNK * D_];
__device__ float g_cBi[B_ * NCHUNK * D_];
__device__ float g_carR[B_ * NCHUNK * D_];
__device__ float g_carI[B_ * NCHUNK * D_];

// tf32-rounded operands (fp32 container)
__device__ float g_xt [(size_t)M1 * K1];
__device__ float g_w1t[(size_t)N1 * K1];    // W_in^T  [4096,1024]
__device__ float g_yt [(size_t)M1 * K2];    // scan+LN output, tf32-rounded
__device__ float g_w2t[(size_t)N2 * K2];    // W_out^T [1024,2048]

// ---------------------------------------------------------------------------
// PTX helpers
// ---------------------------------------------------------------------------
__device__ __forceinline__ uint32_t smem_u32(const void* p) {
    uint32_t a;
    asm("{ .reg .u64 t; cvta.to.shared.u64 t, %1; cvt.u32.u64 %0, t; }"
        : "=r"(a) : "l"(p));
    return a;
}

__device__ __forceinline__ void cp16(uint32_t dst, const void* src) {
    asm volatile("cp.async.cg.shared.global [%0], [%1], 16;\n" :: "r"(dst), "l"(src) : "memory");
}
#define CP_COMMIT() asm volatile("cp.async.commit_group;" ::: "memory")

__device__ __forceinline__ float to_tf32(float x) {
    uint32_t u;
    asm("cvt.rna.tf32.f32 %0, %1;" : "=r"(u) : "f"(x));
    return __uint_as_float(u);
}

__device__ __forceinline__ void mma_tf32(float* d, const uint32_t* a, uint32_t b0, uint32_t b1) {
    asm volatile(
        "mma.sync.aligned.m16n8k8.row.col.f32.tf32.tf32.f32 "
        "{%0,%1,%2,%3}, {%4,%5,%6,%7}, {%8,%9}, {%0,%1,%2,%3};"
        : "+f"(d[0]), "+f"(d[1]), "+f"(d[2]), "+f"(d[3])
        : "r"(a[0]), "r"(a[1]), "r"(a[2]), "r"(a[3]), "r"(b0), "r"(b1));
}

// ---------------------------------------------------------------------------
// tf32 MMA GEMM (unchanged from R16): C[M,N] = A[M,K] @ Bt[N,K]^T + bias
// 128x128 tile, BK=32, 4 warps 2m x 2n (64x64), 3-stage ring, 2 CTAs/SM.
// ---------------------------------------------------------------------------
constexpr int NSTAGE    = 3;
constexpr int SLOT      = 32768;
constexpr int GEMM_SMEM = NSTAGE * SLOT;   // 96 KB -> 2 CTAs/SM

__device__ __forceinline__ uint32_t sw32(int row, int ch) {
    return (uint32_t)(row * 128 + (((ch) ^ (row & 7)) << 4));
}

__global__ __launch_bounds__(128, 2)
void tf32_gemm(int M, int N, int K,
               const float* __restrict__ A, const float* __restrict__ Bt,
               const float* __restrict__ bias, float* __restrict__ C)
{
    extern __shared__ char smem[];
    const uint32_t sb = smem_u32(smem);
    const int tid  = threadIdx.x;
    const int lane = tid & 31;
    const int wid  = tid >> 5;
    const int wm   = wid & 1;
    const int wn   = wid >> 1;

    const int nbx  = N >> 7;
    const int lin  = blockIdx.x;
    const int band = lin / (8 * nbx);
    const int rem  = lin % (8 * nbx);
    const int by   = band * 8 + (rem & 7);
    const int bx   = rem >> 3;

    const size_t arow0 = (size_t)by * 128;
    const size_t brow0 = (size_t)bx * 128;
    const int S = K / 32;

    float acc[4][8][4];
    #pragma unroll
    for (int i = 0; i < 4; i++)
        #pragma unroll
        for (int j = 0; j < 8; j++)
            #pragma unroll
            for (int k = 0; k < 4; k++) acc[i][j][k] = 0.f;

    auto load_stage = [&](int s, int slot) {
        const uint32_t st = sb + (uint32_t)slot * (uint32_t)SLOT;
        const int k0 = s * 32;
        #pragma unroll
        for (int j = 0; j < 8; j++) {
            const int idx = tid + j * 128;
            const int r = idx >> 3, ch = idx & 7;
            cp16(st +          sw32(r, ch), A  + (arow0 + r) * (size_t)K + k0 + ch * 4);
            cp16(st + 16384u + sw32(r, ch), Bt + (brow0 + r) * (size_t)K + k0 + ch * 4);
        }
    };

    const int rA = lane >> 2;
    const int cb = (lane & 3) * 4;

    load_stage(0, 0); CP_COMMIT();
    load_stage(1, 1); CP_COMMIT();

    int slot_c = 0;
    int slot_l = 2;
    for (int s = 0; s < S; s++) {
        asm volatile("cp.async.wait_group 1;" ::: "memory");
        __syncthreads();

        if (s + 2 < S) load_stage(s + 2, slot_l);
        CP_COMMIT();

        const char* baseA = smem + slot_c * SLOT;
        const char* baseB = baseA + 16384;
        #pragma unroll
        for (int ks8 = 0; ks8 < 4; ks8++) {
            const int ch0 = ks8 * 2, ch1 = ch0 + 1;
            const uint32_t x0 = (uint32_t)(((ch0 ^ rA) << 4) + cb);
            const uint32_t x1 = (uint32_t)(((ch1 ^ rA) << 4) + cb);

            uint32_t aF[4][4];
            #pragma unroll
            for (int mi = 0; mi < 4; mi++) {
                const int r0 = wm * 64 + mi * 16 + rA;
                aF[mi][0] = *(const uint32_t*)(baseA + r0 * 128 + x0);
                aF[mi][1] = *(const uint32_t*)(baseA + (r0 + 8) * 128 + x0);
                aF[mi][2] = *(const uint32_t*)(baseA + r0 * 128 + x1);
                aF[mi][3] = *(const uint32_t*)(baseA + (r0 + 8) * 128 + x1);
            }
            #pragma unroll
            for (int np = 0; np < 8; np++) {
                const int rn = wn * 64 + np * 8 + rA;
                const uint32_t b0 = *(const uint32_t*)(baseB + rn * 128 + x0);
                const uint32_t b1 = *(const uint32_t*)(baseB + rn * 128 + x1);
                #pragma unroll
                for (int mi = 0; mi < 4; mi++)
                    mma_tf32(acc[mi][np], aF[mi], b0, b1);
            }
        }
        slot_c = (slot_c == 2) ? 0 : slot_c + 1;
        slot_l = (slot_l == 2) ? 0 : slot_l + 1;
    }

    #pragma unroll
    for (int mi = 0; mi < 4; mi++) {
        const size_t r0 = arow0 + wm * 64 + mi * 16 + (lane >> 2);
        #pragma unroll
        for (int ni = 0; ni < 8; ni++) {
            const int c = bx * 128 + wn * 64 + ni * 8 + (lane & 3) * 2;
            const float b0 = bias[c], b1 = bias[c + 1];
            float2 v0 = make_float2(acc[mi][ni][0] + b0, acc[mi][ni][1] + b1);
            float2 v1 = make_float2(acc[mi][ni][2] + b0, acc[mi][ni][3] + b1);
            *reinterpret_cast<float2*>(C + r0 * (size_t)N + c)       = v0;
            *reinterpret_cast<float2*>(C + (r0 + 8) * (size_t)N + c) = v1;
        }
    }
}

// ---------------------------------------------------------------------------
// fp32 -> tf32 round (elementwise)
// ---------------------------------------------------------------------------
__global__ void round_rows(const float* __restrict__ X, float* __restrict__ Xt, size_t n)
{
    size_t i = ((size_t)blockIdx.x * blockDim.x + threadIdx.x) * 4;
    if (i >= n) return;
    float4 v = *reinterpret_cast<const float4*>(X + i);
    v.x = to_tf32(v.x); v.y = to_tf32(v.y);
    v.z = to_tf32(v.z); v.w = to_tf32(v.w);
    *reinterpret_cast<float4*>(Xt + i) = v;
}

// ---------------------------------------------------------------------------
// W[K,N] -> T[N,K] transpose + tf32 round
// ---------------------------------------------------------------------------
__global__ void transpose_round(const float* __restrict__ W, int K, int N,
                                float* __restrict__ Tt)
{
    __shared__ float tile[32][33];
    int n0 = blockIdx.x * 32, k0 = blockIdx.y * 32;
    int tx = threadIdx.x, ty = threadIdx.y;
    #pragma unroll
    for (int i = 0; i < 32; i += 8)
        tile[ty + i][tx] = W[(size_t)(k0 + ty + i) * N + n0 + tx];
    __syncthreads();
    #pragma unroll
    for (int i = 0; i < 32; i += 8) {
        int nn = ty + i, kk = tx;
        Tt[(size_t)(n0 + nn) * K + k0 + kk] = to_tf32(tile[kk][nn]);
    }
}

// ---------------------------------------------------------------------------
// LRU scan phase 1: per-(b,chunk) local scans, float2 (2 channels/thread).
// 64 chunks x 32 steps.
// ---------------------------------------------------------------------------
__global__ void scan_phase1(const float* __restrict__ nu_log,
                            const float* __restrict__ theta_log,
                            const float* __restrict__ gamma_log)
{
    int idx = blockIdx.x * blockDim.x + threadIdx.x;   // pair index
    int dp = idx % (D_ / 2);
    int c  = (idx / (D_ / 2)) % NCHUNK;
    int b  = idx / ((D_ / 2) * NCHUNK);
    int d0 = dp * 2;

    float fr0, fi0, ga0, fr1, fi1, ga1;
    {
        float nu = expf(-expf(nu_log[d0]));
        float th = expf(theta_log[d0]);
        fr0 = nu * cosf(th); fi0 = nu * sinf(th); ga0 = expf(gamma_log[d0]);
        nu = expf(-expf(nu_log[d0 + 1]));
        th = expf(theta_log[d0 + 1]);
        fr1 = nu * cosf(th); fi1 = nu * sinf(th); ga1 = expf(gamma_log[d0 + 1]);
    }

    const float* up = g_u + (size_t)(b * T_ + c * LCH) * N1;
    float h0r = 0.f, h0i = 0.f, h1r = 0.f, h1i = 0.f;
    #pragma unroll 4
    for (int t = 0; t < LCH; t++) {
        float2 vr = *reinterpret_cast<const float2*>(up + (size_t)t * N1 + d0);
        float2 vi = *reinterpret_cast<const float2*>(up + (size_t)t * N1 + D_ + d0);
        float n0r = fr0 * h0r - fi0 * h0i + ga0 * vr.x;
        float n0i = fr0 * h0i + fi0 * h0r + ga0 * vi.x;
        float n1r = fr1 * h1r - fi1 * h1i + ga1 * vr.y;
        float n1i = fr1 * h1i + fi1 * h1r + ga1 * vi.y;
        h0r = n0r; h0i = n0i; h1r = n1r; h1i = n1i;
    }
    int o = (b * NCHUNK + c) * D_ + d0;
    g_cBr[o] = h0r;     g_cBi[o] = h0i;
    g_cBr[o + 1] = h1r; g_cBi[o + 1] = h1i;
}

// ---------------------------------------------------------------------------
// LRU scan phase 2: combine 64 chunk results per (b,d); f^32 = 5 squarings.
// ---------------------------------------------------------------------------
__global__ void scan_phase2(const float* __restrict__ nu_log,
                            const float* __restrict__ theta_log)
{
    int idx = blockIdx.x * blockDim.x + threadIdx.x;   // b*D + d
    int d = idx % D_;
    int b = idx / D_;

    float nu = expf(-expf(nu_log[d]));
    float th = expf(theta_log[d]);
    float ar = nu * cosf(th);
    float ai = nu * sinf(th);
    #pragma unroll
    for (int s = 0; s < 5; s++) {          // f^32 (LCH=32)
        float nr = ar * ar - ai * ai;
        float ni = 2.f * ar * ai;
        ar = nr; ai = ni;
    }

    float cr = 0.f, ci = 0.f;
    for (int c = 0; c < NCHUNK; c++) {
        int o = (b * NCHUNK + c) * D_ + d;
        g_carR[o] = cr;
        g_carI[o] = ci;
        float br = g_cBr[o], bi = g_cBi[o];
        float nr = ar * cr - ai * ci + br;
        float ni = ar * ci + ai * cr + bi;
        cr = nr; ci = ni;
    }
}

// ---------------------------------------------------------------------------
// Fused scan phase 3 + SiLU gate + LayerNorm(2048) + tf32 round -> g_yt.
// One CTA = one (b, chunk); 1024 threads, thread owns channel d.
// Per timestep: coalesced row read, h update, block-reduce mean/var,
// normalize, write. Next-row loads prefetched over the reduction.
// ---------------------------------------------------------------------------
__global__ __launch_bounds__(1024, 2)
void scan3_ln(const float* __restrict__ nu_log,
              const float* __restrict__ theta_log,
              const float* __restrict__ gamma_log,
              const float* __restrict__ ln_w,
              const float* __restrict__ ln_b)
{
    const int d = threadIdx.x;              // 0..1023
    const int c = blockIdx.x % NCHUNK;
    const int b = blockIdx.x / NCHUNK;

    float fr, fi, ga;
    {
        float nu = expf(-expf(nu_log[d]));
        float th = expf(theta_log[d]);
        fr = nu * cosf(th); fi = nu * sinf(th); ga = expf(gamma_log[d]);
    }
    const float wR = ln_w[d],       bR = ln_b[d];
    const float wI = ln_w[D_ + d],  bI = ln_b[D_ + d];

    const int o = (b * NCHUNK + c) * D_ + d;
    float hr = g_carR[o], hi = g_carI[o];

    const float* up = g_u  + (size_t)(b * T_ + c * LCH) * N1;
    float*       yt = g_yt + (size_t)(b * T_ + c * LCH) * K2;

    __shared__ float sSum[32], sSq[32];
    const int lane = d & 31, wrp = d >> 5;

    // prefetch t=0
    float vr = up[d], vi = up[D_ + d], o1 = up[2 * D_ + d], o2 = up[3 * D_ + d];

    for (int t = 0; t < LCH; t++) {
        // recurrence + gate
        float nr = fr * hr - fi * hi + ga * vr;
        float ni = fr * hi + fi * hr + ga * vi;
        hr = nr; hi = ni;
        float s1 = o1 / (1.f + expf(-o1));
        float s2 = o2 / (1.f + expf(-o2));
        float yr = hr * s1;
        float yi = hi * s2;

        // prefetch next row (overlaps reduction)
        if (t + 1 < LCH) {
            const float* upn = up + (size_t)(t + 1) * N1;
            vr = upn[d]; vi = upn[D_ + d];
            o1 = upn[2 * D_ + d]; o2 = upn[3 * D_ + d];
        }

        // block reduction of sum & sumsq over 2048 values
        float lsum = yr + yi;
        float lsq  = yr * yr + yi * yi;
        #pragma unroll
        for (int off = 16; off > 0; off >>= 1) {
            lsum += __shfl_xor_sync(0xFFFFFFFF, lsum, off);
            lsq  += __shfl_xor_sync(0xFFFFFFFF, lsq,  off);
        }
        if (lane == 0) { sSum[wrp] = lsum; sSq[wrp] = lsq; }
        __syncthreads();
        if (wrp == 0) {
            float a = sSum[lane], q = sSq[lane];
            #pragma unroll
            for (int off = 16; off > 0; off >>= 1) {
                a += __shfl_xor_sync(0xFFFFFFFF, a, off);
                q += __shfl_xor_sync(0xFFFFFFFF, q, off);
            }
            if (lane == 0) { sSum[0] = a; sSq[0] = q; }
        }
        __syncthreads();
        const float mean = sSum[0] * (1.f / K2);
        const float var  = sSq[0] * (1.f / K2) - mean * mean;
        const float inv  = rsqrtf(var + 1e-5f);
        __syncthreads();   // protect sSum/sSq reuse next iteration

        float* yrow = yt + (size_t)t * K2;
        yrow[d]      = to_tf32((yr - mean) * inv * wR + bR);
        yrow[D_ + d] = to_tf32((yi - mean) * inv * wI + bI);
    }
}

// ---------------------------------------------------------------------------
// Launch
// ---------------------------------------------------------------------------
extern "C" void kernel_launch(void* const* d_in, const int* in_sizes, int n_in,
                              void* d_out, int out_size)
{
    const float* x         = (const float*)d_in[0];
    const float* W_in      = (const float*)d_in[1];
    const float* b_in      = (const float*)d_in[2];
    const float* nu_log    = (const float*)d_in[3];
    const float* theta_log = (const float*)d_in[4];
    const float* gamma_log = (const float*)d_in[5];
    const float* ln_w      = (const float*)d_in[6];
    const float* ln_b      = (const float*)d_in[7];
    const float* W_out     = (const float*)d_in[8];
    const float* b_out     = (const float*)d_in[9];
    float* out = (float*)d_out;

    float *u_ptr, *xt, *w1t, *yt, *w2t;
    cudaGetSymbolAddress((void**)&u_ptr, g_u);
    cudaGetSymbolAddress((void**)&xt,  g_xt);
    cudaGetSymbolAddress((void**)&w1t, g_w1t);
    cudaGetSymbolAddress((void**)&yt,  g_yt);
    cudaGetSymbolAddress((void**)&w2t, g_w2t);

    cudaFuncSetAttribute(tf32_gemm, cudaFuncAttributeMaxDynamicSharedMemorySize, GEMM_SMEM);

    // operand prep for GEMM1
    {
        size_t n = (size_t)M1 * K1;
        round_rows<<<(unsigned)((n / 4 + 255) / 256), 256>>>(x, xt, n);
        dim3 g(N1 / 32, K1 / 32);
        transpose_round<<<g, dim3(32, 8)>>>(W_in, K1, N1, w1t);
    }
    // GEMM1: u = x @ W_in + b_in
    {
        int grid = (M1 / 128) * (N1 / 128);
        tf32_gemm<<<grid, 128, GEMM_SMEM>>>(M1, N1, K1, xt, w1t, b_in, u_ptr);
    }
    // Scan phases 1-2
    {
        int pairs = B_ * NCHUNK * (D_ / 2);
        scan_phase1<<<pairs / 256, 256>>>(nu_log, theta_log, gamma_log);
        scan_phase2<<<(B_ * D_) / 256, 256>>>(nu_log, theta_log);
    }
    // Fused scan phase 3 + SiLU + LayerNorm + tf32 round
    scan3_ln<<<B_ * NCHUNK, 1024>>>(nu_log, theta_log, gamma_log, ln_w, ln_b);

    // operand prep for GEMM2 (weights only)
    {
        dim3 g(N2 / 32, K2 / 32);
        transpose_round<<<g, dim3(32, 8)>>>(W_out, K2, N2, w2t);
    }
    // GEMM2: out = y @ W_out + b_out
    {
        int grid = (M1 / 128) * (N2 / 128);
        tf32_gemm<<<grid, 128, GEMM_SMEM>>>(M1, N2, K2, yt, w2t, b_out, out);
    }
}